// round 2
// baseline (speedup 1.0000x reference)
#include <cuda_runtime.h>
#include <cuda_bf16.h>
#include <stdint.h>

#define Hdim 2048
#define HH   (Hdim * Hdim)        // 4194304
#define NIDX 2000000
#define NB   256

// ---------------- device scratch (no allocations allowed) ----------------
__device__ unsigned int  g_hist[6 * NB];     // [0..2]=dst(ref_masked), [3..5]=ref(target_masked)
__device__ unsigned char g_touched[HH];
__device__ float         g_table[3 * NB];
__device__ double        g_acc;

// ---------------- helpers ----------------
__device__ __forceinline__ float dn255(float x) {
    float v = (x + 1.0f) * 0.5f;
    v = fminf(fmaxf(v, 0.0f), 1.0f);
    return v * 255.0f;
}
__device__ __forceinline__ int binof(float v) {
    // v in [0,255]; trunc == floor for nonneg; clip for safety
    int b = (int)v;
    b = b < 0 ? 0 : b;
    return b > 255 ? 255 : b;
}
__device__ __forceinline__ float warpReduceSum(float v) {
    #pragma unroll
    for (int o = 16; o > 0; o >>= 1) v += __shfl_down_sync(0xffffffffu, v, o);
    return v;
}

// ---------------- K0: init ----------------
__global__ void __launch_bounds__(256) k_init() {
    int i = blockIdx.x * blockDim.x + threadIdx.x;
    int stride = gridDim.x * blockDim.x;
    uint4* t16 = reinterpret_cast<uint4*>(g_touched);
    const uint4 z = {0u, 0u, 0u, 0u};
    for (int j = i; j < HH / 16; j += stride) t16[j] = z;
    if (i < 6 * NB) g_hist[i] = 0u;
    if (i == 0) g_acc = 0.0;
}

// ---------------- K1: gather + histograms + touched scatter ----------------
__global__ void __launch_bounds__(256) k_gather_hist(
    const float* __restrict__ ref, const float* __restrict__ tgt,
    const float* __restrict__ msrc, const float* __restrict__ mtar,
    const int* __restrict__ i0, const int* __restrict__ i1,
    const int* __restrict__ i2, const int* __restrict__ i3)
{
    __shared__ unsigned int sh[6 * NB];
    for (int i = threadIdx.x; i < 6 * NB; i += blockDim.x) sh[i] = 0u;
    __syncthreads();

    unsigned int c0[6]   = {0, 0, 0, 0, 0, 0};
    unsigned int c255[6] = {0, 0, 0, 0, 0, 0};

    int stride = gridDim.x * blockDim.x;
    for (int k = blockIdx.x * blockDim.x + threadIdx.x; k < NIDX; k += stride) {
        int p = i0[k] * Hdim + i1[k];
        int q = i2[k] * Hdim + i3[k];
        g_touched[p] = 1;
        float ms = __ldg(msrc + p);
        float mt = __ldg(mtar + q);
        // issue all 6 image loads up front for MLP
        float r0 = __ldg(ref + 0 * HH + p);
        float r1 = __ldg(ref + 1 * HH + p);
        float r2 = __ldg(ref + 2 * HH + p);
        float t0 = __ldg(tgt + 0 * HH + q);
        float t1 = __ldg(tgt + 1 * HH + q);
        float t2 = __ldg(tgt + 2 * HH + q);
        float rv[3] = {r0, r1, r2};
        float tv[3] = {t0, t1, t2};
        #pragma unroll
        for (int c = 0; c < 3; c++) {
            int b = binof(dn255(rv[c]) * ms);
            if (b == 0)        c0[c]++;
            else if (b == 255) c255[c]++;
            else               atomicAdd(&sh[c * NB + b], 1u);
            int b2 = binof(dn255(tv[c]) * mt);
            if (b2 == 0)        c0[3 + c]++;
            else if (b2 == 255) c255[3 + c]++;
            else                atomicAdd(&sh[(3 + c) * NB + b2], 1u);
        }
    }
    #pragma unroll
    for (int h = 0; h < 6; h++) {
        if (c0[h])   atomicAdd(&sh[h * NB + 0],   c0[h]);
        if (c255[h]) atomicAdd(&sh[h * NB + 255], c255[h]);
    }
    __syncthreads();
    for (int i = threadIdx.x; i < 6 * NB; i += blockDim.x) {
        unsigned int v = sh[i];
        if (v) atomicAdd(&g_hist[i], v);
    }
}

// ---------------- K2: CDFs + transfer tables (single block, 256 threads) ----------------
__global__ void k_tables() {
    __shared__ float r[3][NB];   // cdf_dst
    __shared__ float a[3][NB];   // cdf_ref
    if (threadIdx.x < 6) {
        int h = threadIdx.x;
        float run = 0.0f;
        float tmp[NB];
        for (int j = 0; j < NB; j++) {
            run += (float)g_hist[h * NB + j];   // exact: integers < 2^24
            tmp[j] = run;
        }
        float tot = run;
        for (int j = 0; j < NB; j++) {
            float v = tmp[j] / tot;
            if (h < 3) r[h][j] = v; else a[h - 3][j] = v;
        }
    }
    __syncthreads();
    int i = threadIdx.x;
    #pragma unroll
    for (int c = 0; c < 3; c++) {
        float tbl;
        if (i == 0)           tbl = 0.0f;
        else if (i == NB - 1) tbl = 255.0f;
        else {
            float ri = r[c][i];
            int j = -1;
            for (int jj = 1; jj < NB; jj++) {
                if (ri >= a[c][jj - 1] && ri <= a[c][jj]) { j = jj; break; }
            }
            tbl = (j >= 0) ? (float)j : (float)i;
        }
        g_table[c * NB + i] = tbl;
    }
}

// ---------------- K3: loss over all pixels (vectorized float4) ----------------
__global__ void __launch_bounds__(256) k_loss(
    const float* __restrict__ inp, const float* __restrict__ ref,
    const float* __restrict__ msrc)
{
    __shared__ float stab[3 * NB];
    for (int i = threadIdx.x; i < 3 * NB; i += blockDim.x) stab[i] = g_table[i];
    __syncthreads();

    const float4* m4 = reinterpret_cast<const float4*>(msrc);
    const float4* in4 = reinterpret_cast<const float4*>(inp);
    const float4* rf4 = reinterpret_cast<const float4*>(ref);
    const uchar4* t4 = reinterpret_cast<const uchar4*>(g_touched);

    float acc = 0.0f;
    int stride = gridDim.x * blockDim.x;
    const int NP4 = HH / 4;
    for (int idx = blockIdx.x * blockDim.x + threadIdx.x; idx < NP4; idx += stride) {
        float4 ms = m4[idx];
        uchar4 tc = t4[idx];
        float msA[4] = {ms.x, ms.y, ms.z, ms.w};
        unsigned char tA[4] = {tc.x, tc.y, tc.z, tc.w};
        #pragma unroll
        for (int c = 0; c < 3; c++) {
            float4 iv = in4[c * NP4 + idx];
            float4 rv = rf4[c * NP4 + idx];
            float ivA[4] = {iv.x, iv.y, iv.z, iv.w};
            float rvA[4] = {rv.x, rv.y, rv.z, rv.w};
            #pragma unroll
            for (int l = 0; l < 4; l++) {
                float im = dn255(ivA[l]) * msA[l];
                float rm = dn255(rvA[l]) * msA[l];
                float match = tA[l] ? stab[c * NB + binof(rm)] : rm;
                acc += fabsf(im - match);
            }
        }
    }

    // block reduce -> double atomic
    float s = warpReduceSum(acc);
    __shared__ float ws[32];
    int lane = threadIdx.x & 31, w = threadIdx.x >> 5;
    if (lane == 0) ws[w] = s;
    __syncthreads();
    if (w == 0) {
        float v = (lane < (int)(blockDim.x >> 5)) ? ws[lane] : 0.0f;
        v = warpReduceSum(v);
        if (lane == 0) atomicAdd(&g_acc, (double)v);
    }
}

// ---------------- K4: finalize ----------------
__global__ void k_finalize(float* out) {
    out[0] = (float)(g_acc / (double)(3.0 * (double)HH));
}

// ---------------- launch ----------------
extern "C" void kernel_launch(void* const* d_in, const int* in_sizes, int n_in,
                              void* d_out, int out_size)
{
    const float* input_data = (const float*)d_in[0];
    const float* target_data = (const float*)d_in[1];
    const float* ref = (const float*)d_in[2];
    const float* mask_src = (const float*)d_in[3];
    const float* mask_tar = (const float*)d_in[4];
    const int* idx0 = (const int*)d_in[5];
    const int* idx1 = (const int*)d_in[6];
    const int* idx2 = (const int*)d_in[7];
    const int* idx3 = (const int*)d_in[8];
    float* out = (float*)d_out;

    k_init<<<2048, 256>>>();
    k_gather_hist<<<1184, 256>>>(ref, target_data, mask_src, mask_tar,
                                 idx0, idx1, idx2, idx3);
    k_tables<<<1, 256>>>();
    k_loss<<<2048, 256>>>(input_data, ref, mask_src);
    k_finalize<<<1, 1>>>(out);
}

// round 3
// speedup vs baseline: 1.0109x; 1.0109x over previous
#include <cuda_runtime.h>
#include <cuda_bf16.h>
#include <stdint.h>

#define Hdim 2048
#define HH   (Hdim * Hdim)        // 4194304
#define NIDX 2000000
#define NB   256

// ---------------- device scratch (no allocations allowed) ----------------
__device__ unsigned int g_hist[6 * NB];   // [0..2]=dst(ref_masked), [3..5]=ref(target_masked)
__device__ unsigned int g_cnt_p[HH];      // occurrences of (idx0,idx1)
__device__ unsigned int g_cnt_q[HH];      // occurrences of (idx2,idx3)
__device__ float        g_table[3 * NB];
__device__ double       g_acc;

// ---------------- helpers ----------------
__device__ __forceinline__ float dn255(float x) {
    float v = (x + 1.0f) * 0.5f;
    v = fminf(fmaxf(v, 0.0f), 1.0f);
    return v * 255.0f;
}
__device__ __forceinline__ int binof(float v) {
    int b = (int)v;
    b = b < 0 ? 0 : b;
    return b > 255 ? 255 : b;
}
__device__ __forceinline__ float warpReduceSum(float v) {
    #pragma unroll
    for (int o = 16; o > 0; o >>= 1) v += __shfl_down_sync(0xffffffffu, v, o);
    return v;
}

// ---------------- K0: init (tiny: hist + acc only; counts self-reset) ----------------
__global__ void k_init() {
    int i = blockIdx.x * blockDim.x + threadIdx.x;
    if (i < 6 * NB) g_hist[i] = 0u;
    if (i == 0) g_acc = 0.0;
}

// ---------------- K1a: scatter counts (no-return atomics; latency-free) ----------------
__global__ void __launch_bounds__(256) k_scatter(
    const int* __restrict__ i0, const int* __restrict__ i1,
    const int* __restrict__ i2, const int* __restrict__ i3)
{
    int t = blockIdx.x * blockDim.x + threadIdx.x;
    int k = t * 4;
    if (k + 3 >= NIDX) {                      // (never taken: NIDX % 4 == 0, exact grid)
        for (; k < NIDX; k++) {
            atomicAdd(&g_cnt_p[i0[k] * Hdim + i1[k]], 1u);
            atomicAdd(&g_cnt_q[i2[k] * Hdim + i3[k]], 1u);
        }
        return;
    }
    int4 a0 = *reinterpret_cast<const int4*>(i0 + k);
    int4 a1 = *reinterpret_cast<const int4*>(i1 + k);
    int4 a2 = *reinterpret_cast<const int4*>(i2 + k);
    int4 a3 = *reinterpret_cast<const int4*>(i3 + k);
    atomicAdd(&g_cnt_p[a0.x * Hdim + a1.x], 1u);
    atomicAdd(&g_cnt_p[a0.y * Hdim + a1.y], 1u);
    atomicAdd(&g_cnt_p[a0.z * Hdim + a1.z], 1u);
    atomicAdd(&g_cnt_p[a0.w * Hdim + a1.w], 1u);
    atomicAdd(&g_cnt_q[a2.x * Hdim + a3.x], 1u);
    atomicAdd(&g_cnt_q[a2.y * Hdim + a3.y], 1u);
    atomicAdd(&g_cnt_q[a2.z * Hdim + a3.z], 1u);
    atomicAdd(&g_cnt_q[a2.w * Hdim + a3.w], 1u);
}

// ---------------- K1b: streaming weighted histogram ----------------
__global__ void __launch_bounds__(256) k_hist(
    const float* __restrict__ ref, const float* __restrict__ tgt,
    const float* __restrict__ msrc, const float* __restrict__ mtar)
{
    __shared__ unsigned int sh[6 * NB];
    for (int i = threadIdx.x; i < 6 * NB; i += blockDim.x) sh[i] = 0u;
    __syncthreads();

    unsigned int c0[6]   = {0, 0, 0, 0, 0, 0};
    unsigned int c255[6] = {0, 0, 0, 0, 0, 0};

    const int NP4 = HH / 4;
    int idx = blockIdx.x * blockDim.x + threadIdx.x;   // exactly NP4 threads
    if (idx < NP4) {
        uint4* cp4 = reinterpret_cast<uint4*>(g_cnt_p);
        uint4* cq4 = reinterpret_cast<uint4*>(g_cnt_q);
        const float4* m4  = reinterpret_cast<const float4*>(msrc);
        const float4* mt4 = reinterpret_cast<const float4*>(mtar);
        const float4* rf4 = reinterpret_cast<const float4*>(ref);
        const float4* tg4 = reinterpret_cast<const float4*>(tgt);

        uint4 cp = cp4[idx];
        uint4 cq = cq4[idx];
        cq4[idx] = make_uint4(0u, 0u, 0u, 0u);   // reset for next replay (cp reset in k_loss)
        float4 ms = m4[idx];
        float4 mt = mt4[idx];
        unsigned int cpA[4] = {cp.x, cp.y, cp.z, cp.w};
        unsigned int cqA[4] = {cq.x, cq.y, cq.z, cq.w};
        float msA[4] = {ms.x, ms.y, ms.z, ms.w};
        float mtA[4] = {mt.x, mt.y, mt.z, mt.w};

        #pragma unroll
        for (int c = 0; c < 3; c++) {
            float4 rv = rf4[c * NP4 + idx];
            float4 tv = tg4[c * NP4 + idx];
            float rvA[4] = {rv.x, rv.y, rv.z, rv.w};
            float tvA[4] = {tv.x, tv.y, tv.z, tv.w};
            #pragma unroll
            for (int l = 0; l < 4; l++) {
                unsigned int w = cpA[l];
                if (w) {
                    int b = binof(dn255(rvA[l]) * msA[l]);
                    if (b == 0)        c0[c] += w;
                    else if (b == 255) c255[c] += w;
                    else               atomicAdd(&sh[c * NB + b], w);
                }
                unsigned int w2 = cqA[l];
                if (w2) {
                    int b = binof(dn255(tvA[l]) * mtA[l]);
                    if (b == 0)        c0[3 + c] += w2;
                    else if (b == 255) c255[3 + c] += w2;
                    else               atomicAdd(&sh[(3 + c) * NB + b], w2);
                }
            }
        }
    }
    #pragma unroll
    for (int h = 0; h < 6; h++) {
        if (c0[h])   atomicAdd(&sh[h * NB + 0],   c0[h]);
        if (c255[h]) atomicAdd(&sh[h * NB + 255], c255[h]);
    }
    __syncthreads();
    for (int i = threadIdx.x; i < 6 * NB; i += blockDim.x) {
        unsigned int v = sh[i];
        if (v) atomicAdd(&g_hist[i], v);
    }
}

// ---------------- K2: CDFs + transfer tables (single block, 256 threads) ----------------
__global__ void k_tables() {
    __shared__ float r[3][NB];   // cdf_dst
    __shared__ float a[3][NB];   // cdf_ref
    if (threadIdx.x < 6) {
        int h = threadIdx.x;
        float run = 0.0f;
        float tmp[NB];
        for (int j = 0; j < NB; j++) {
            run += (float)g_hist[h * NB + j];   // exact: integers < 2^24
            tmp[j] = run;
        }
        float tot = run;
        for (int j = 0; j < NB; j++) {
            float v = tmp[j] / tot;
            if (h < 3) r[h][j] = v; else a[h - 3][j] = v;
        }
    }
    __syncthreads();
    int i = threadIdx.x;
    #pragma unroll
    for (int c = 0; c < 3; c++) {
        float tbl;
        if (i == 0)           tbl = 0.0f;
        else if (i == NB - 1) tbl = 255.0f;
        else {
            float ri = r[c][i];
            int j = -1;
            for (int jj = 1; jj < NB; jj++) {
                if (ri >= a[c][jj - 1] && ri <= a[c][jj]) { j = jj; break; }
            }
            tbl = (j >= 0) ? (float)j : (float)i;
        }
        g_table[c * NB + i] = tbl;
    }
}

// ---------------- K3: loss over all pixels (vectorized float4) ----------------
__global__ void __launch_bounds__(256) k_loss(
    const float* __restrict__ inp, const float* __restrict__ ref,
    const float* __restrict__ msrc)
{
    __shared__ float stab[3 * NB];
    for (int i = threadIdx.x; i < 3 * NB; i += blockDim.x) stab[i] = g_table[i];
    __syncthreads();

    const float4* m4  = reinterpret_cast<const float4*>(msrc);
    const float4* in4 = reinterpret_cast<const float4*>(inp);
    const float4* rf4 = reinterpret_cast<const float4*>(ref);
    uint4* cp4 = reinterpret_cast<uint4*>(g_cnt_p);

    float acc = 0.0f;
    int stride = gridDim.x * blockDim.x;
    const int NP4 = HH / 4;
    for (int idx = blockIdx.x * blockDim.x + threadIdx.x; idx < NP4; idx += stride) {
        float4 ms = m4[idx];
        uint4 cp = cp4[idx];
        cp4[idx] = make_uint4(0u, 0u, 0u, 0u);   // reset for next replay
        float msA[4] = {ms.x, ms.y, ms.z, ms.w};
        unsigned int tA[4] = {cp.x, cp.y, cp.z, cp.w};
        #pragma unroll
        for (int c = 0; c < 3; c++) {
            float4 iv = in4[c * NP4 + idx];
            float4 rv = rf4[c * NP4 + idx];
            float ivA[4] = {iv.x, iv.y, iv.z, iv.w};
            float rvA[4] = {rv.x, rv.y, rv.z, rv.w};
            #pragma unroll
            for (int l = 0; l < 4; l++) {
                float im = dn255(ivA[l]) * msA[l];
                float rm = dn255(rvA[l]) * msA[l];
                float match = tA[l] ? stab[c * NB + binof(rm)] : rm;
                acc += fabsf(im - match);
            }
        }
    }

    // block reduce -> double atomic
    float s = warpReduceSum(acc);
    __shared__ float ws[32];
    int lane = threadIdx.x & 31, w = threadIdx.x >> 5;
    if (lane == 0) ws[w] = s;
    __syncthreads();
    if (w == 0) {
        float v = (lane < (int)(blockDim.x >> 5)) ? ws[lane] : 0.0f;
        v = warpReduceSum(v);
        if (lane == 0) atomicAdd(&g_acc, (double)v);
    }
}

// ---------------- K4: finalize ----------------
__global__ void k_finalize(float* out) {
    out[0] = (float)(g_acc / (double)(3.0 * (double)HH));
}

// ---------------- launch ----------------
extern "C" void kernel_launch(void* const* d_in, const int* in_sizes, int n_in,
                              void* d_out, int out_size)
{
    const float* input_data  = (const float*)d_in[0];
    const float* target_data = (const float*)d_in[1];
    const float* ref         = (const float*)d_in[2];
    const float* mask_src    = (const float*)d_in[3];
    const float* mask_tar    = (const float*)d_in[4];
    const int* idx0 = (const int*)d_in[5];
    const int* idx1 = (const int*)d_in[6];
    const int* idx2 = (const int*)d_in[7];
    const int* idx3 = (const int*)d_in[8];
    float* out = (float*)d_out;

    k_init<<<6, 256>>>();
    k_scatter<<<(NIDX / 4 + 255) / 256, 256>>>(idx0, idx1, idx2, idx3);
    k_hist<<<(HH / 4 + 255) / 256, 256>>>(ref, target_data, mask_src, mask_tar);
    k_tables<<<1, 256>>>();
    k_loss<<<2048, 256>>>(input_data, ref, mask_src);
    k_finalize<<<1, 1>>>(out);
}

// round 4
// speedup vs baseline: 1.4351x; 1.4197x over previous
#include <cuda_runtime.h>
#include <cuda_bf16.h>
#include <stdint.h>

#define Hdim 2048
#define HH   (Hdim * Hdim)        // 4194304
#define NIDX 2000000
#define NB   256

// ---------------- device scratch (no allocations allowed) ----------------
__device__ unsigned int  g_hist[6 * NB];      // [0..2]=dst(ref_masked), [3..5]=ref(target_masked)
__device__ unsigned int  g_bin_ref[HH];       // packed 3-channel bins of ref_masked
__device__ unsigned int  g_bin_tgt[HH];       // packed 3-channel bins of target_masked
__device__ unsigned char g_touched[HH];       // zero-init at load; reset by k_loss each replay
__device__ float         g_table[3 * NB];
__device__ double        g_acc;

// ---------------- helpers ----------------
__device__ __forceinline__ float dn255(float x) {
    float v = (x + 1.0f) * 0.5f;
    v = fminf(fmaxf(v, 0.0f), 1.0f);
    return v * 255.0f;
}
__device__ __forceinline__ unsigned int binof(float v) {
    int b = (int)v;                  // v >= 0, trunc == floor
    b = b < 0 ? 0 : b;
    return (unsigned int)(b > 255 ? 255 : b);
}
__device__ __forceinline__ float warpReduceSum(float v) {
    #pragma unroll
    for (int o = 16; o > 0; o >>= 1) v += __shfl_down_sync(0xffffffffu, v, o);
    return v;
}

// ---------------- K1: compute packed per-pixel bins (coalesced stream) ----------------
__global__ void __launch_bounds__(256) k_binify(
    const float* __restrict__ ref, const float* __restrict__ tgt,
    const float* __restrict__ msrc, const float* __restrict__ mtar)
{
    // fold tiny init into block 0 (hist not consumed until k_sample)
    if (blockIdx.x == 0) {
        for (int i = threadIdx.x; i < 6 * NB; i += blockDim.x) g_hist[i] = 0u;
        if (threadIdx.x == 0) g_acc = 0.0;
    }

    const int NP4 = HH / 4;
    int idx = blockIdx.x * blockDim.x + threadIdx.x;    // exactly NP4 threads launched
    if (idx >= NP4) return;

    const float4* m4  = reinterpret_cast<const float4*>(msrc);
    const float4* mt4 = reinterpret_cast<const float4*>(mtar);
    const float4* rf4 = reinterpret_cast<const float4*>(ref);
    const float4* tg4 = reinterpret_cast<const float4*>(tgt);

    float4 ms = m4[idx];
    float4 mt = mt4[idx];
    float msA[4] = {ms.x, ms.y, ms.z, ms.w};
    float mtA[4] = {mt.x, mt.y, mt.z, mt.w};

    unsigned int pr[4] = {0u, 0u, 0u, 0u};
    unsigned int pt[4] = {0u, 0u, 0u, 0u};
    #pragma unroll
    for (int c = 0; c < 3; c++) {
        float4 rv = rf4[c * NP4 + idx];
        float4 tv = tg4[c * NP4 + idx];
        float rvA[4] = {rv.x, rv.y, rv.z, rv.w};
        float tvA[4] = {tv.x, tv.y, tv.z, tv.w};
        #pragma unroll
        for (int l = 0; l < 4; l++) {
            pr[l] |= binof(dn255(rvA[l]) * msA[l]) << (8 * c);
            pt[l] |= binof(dn255(tvA[l]) * mtA[l]) << (8 * c);
        }
    }
    reinterpret_cast<uint4*>(g_bin_ref)[idx] = make_uint4(pr[0], pr[1], pr[2], pr[3]);
    reinterpret_cast<uint4*>(g_bin_tgt)[idx] = make_uint4(pt[0], pt[1], pt[2], pt[3]);
}

// ---------------- K2: sample pass — L2-resident random u32 loads + shared hist ----------------
__global__ void __launch_bounds__(256) k_sample(
    const int* __restrict__ i0, const int* __restrict__ i1,
    const int* __restrict__ i2, const int* __restrict__ i3)
{
    __shared__ unsigned int sh[6 * NB];
    for (int i = threadIdx.x; i < 6 * NB; i += blockDim.x) sh[i] = 0u;
    __syncthreads();

    unsigned int c0[6]   = {0, 0, 0, 0, 0, 0};
    unsigned int c255[6] = {0, 0, 0, 0, 0, 0};

    int t = blockIdx.x * blockDim.x + threadIdx.x;
    int k = t * 4;
    if (k + 3 < NIDX) {
        int4 a0 = *reinterpret_cast<const int4*>(i0 + k);
        int4 a1 = *reinterpret_cast<const int4*>(i1 + k);
        int4 a2 = *reinterpret_cast<const int4*>(i2 + k);
        int4 a3 = *reinterpret_cast<const int4*>(i3 + k);
        int pA[4] = {a0.x * Hdim + a1.x, a0.y * Hdim + a1.y,
                     a0.z * Hdim + a1.z, a0.w * Hdim + a1.w};
        int qA[4] = {a2.x * Hdim + a3.x, a2.y * Hdim + a3.y,
                     a2.z * Hdim + a3.z, a2.w * Hdim + a3.w};
        // fire all independent random accesses up front (MLP=8 loads + 4 stores)
        unsigned int wr[4], wt[4];
        #pragma unroll
        for (int l = 0; l < 4; l++) {
            g_touched[pA[l]] = 1;
            wr[l] = __ldg(g_bin_ref + pA[l]);
            wt[l] = __ldg(g_bin_tgt + qA[l]);
        }
        #pragma unroll
        for (int l = 0; l < 4; l++) {
            #pragma unroll
            for (int c = 0; c < 3; c++) {
                unsigned int b = (wr[l] >> (8 * c)) & 255u;
                if (b == 0u)        c0[c]++;
                else if (b == 255u) c255[c]++;
                else                atomicAdd(&sh[c * NB + b], 1u);
                unsigned int b2 = (wt[l] >> (8 * c)) & 255u;
                if (b2 == 0u)        c0[3 + c]++;
                else if (b2 == 255u) c255[3 + c]++;
                else                 atomicAdd(&sh[(3 + c) * NB + b2], 1u);
            }
        }
    } else {
        for (; k < NIDX; k++) {
            int p = i0[k] * Hdim + i1[k];
            int q = i2[k] * Hdim + i3[k];
            g_touched[p] = 1;
            unsigned int wr = __ldg(g_bin_ref + p);
            unsigned int wt = __ldg(g_bin_tgt + q);
            #pragma unroll
            for (int c = 0; c < 3; c++) {
                unsigned int b = (wr >> (8 * c)) & 255u;
                if (b == 0u)        c0[c]++;
                else if (b == 255u) c255[c]++;
                else                atomicAdd(&sh[c * NB + b], 1u);
                unsigned int b2 = (wt >> (8 * c)) & 255u;
                if (b2 == 0u)        c0[3 + c]++;
                else if (b2 == 255u) c255[3 + c]++;
                else                 atomicAdd(&sh[(3 + c) * NB + b2], 1u);
            }
        }
    }

    #pragma unroll
    for (int h = 0; h < 6; h++) {
        if (c0[h])   atomicAdd(&sh[h * NB + 0],   c0[h]);
        if (c255[h]) atomicAdd(&sh[h * NB + 255], c255[h]);
    }
    __syncthreads();
    for (int i = threadIdx.x; i < 6 * NB; i += blockDim.x) {
        unsigned int v = sh[i];
        if (v) atomicAdd(&g_hist[i], v);
    }
}

// ---------------- K3: CDFs (parallel integer scan) + transfer tables ----------------
__global__ void k_tables() {
    __shared__ unsigned int s0[NB], s1[NB];
    __shared__ float r[3][NB];   // cdf_dst
    __shared__ float a[3][NB];   // cdf_ref
    int i = threadIdx.x;

    for (int h = 0; h < 6; h++) {
        s0[i] = g_hist[h * NB + i];
        __syncthreads();
        // Hillis-Steele inclusive scan, 8 steps, ping-pong (exact: integer adds)
        unsigned int* src = s0; unsigned int* dst = s1;
        #pragma unroll
        for (int off = 1; off < NB; off <<= 1) {
            unsigned int v = src[i];
            if (i >= off) v += src[i - off];
            dst[i] = v;
            __syncthreads();
            unsigned int* tmpp = src; src = dst; dst = tmpp;
        }
        float tot = (float)src[NB - 1];
        float v = (float)src[i] / tot;        // matches jnp: exact int in f32, then divide
        if (h < 3) r[h][i] = v; else a[h - 3][i] = v;
        __syncthreads();
    }

    #pragma unroll
    for (int c = 0; c < 3; c++) {
        float tbl;
        if (i == 0)           tbl = 0.0f;
        else if (i == NB - 1) tbl = 255.0f;
        else {
            float ri = r[c][i];
            int j = -1;
            for (int jj = 1; jj < NB; jj++) {
                if (ri >= a[c][jj - 1] && ri <= a[c][jj]) { j = jj; break; }
            }
            tbl = (j >= 0) ? (float)j : (float)i;
        }
        g_table[c * NB + i] = tbl;
    }
}

// ---------------- K4: loss over all pixels (vectorized float4) ----------------
__global__ void __launch_bounds__(256) k_loss(
    const float* __restrict__ inp, const float* __restrict__ ref,
    const float* __restrict__ msrc)
{
    __shared__ float stab[3 * NB];
    for (int i = threadIdx.x; i < 3 * NB; i += blockDim.x) stab[i] = g_table[i];
    __syncthreads();

    const float4* m4  = reinterpret_cast<const float4*>(msrc);
    const float4* in4 = reinterpret_cast<const float4*>(inp);
    const float4* rf4 = reinterpret_cast<const float4*>(ref);
    uchar4* t4 = reinterpret_cast<uchar4*>(g_touched);

    float acc = 0.0f;
    int stride = gridDim.x * blockDim.x;
    const int NP4 = HH / 4;
    for (int idx = blockIdx.x * blockDim.x + threadIdx.x; idx < NP4; idx += stride) {
        float4 ms = m4[idx];
        uchar4 tc = t4[idx];
        t4[idx] = make_uchar4(0, 0, 0, 0);    // reset for next replay
        float msA[4] = {ms.x, ms.y, ms.z, ms.w};
        unsigned char tA[4] = {tc.x, tc.y, tc.z, tc.w};
        #pragma unroll
        for (int c = 0; c < 3; c++) {
            float4 iv = in4[c * NP4 + idx];
            float4 rv = rf4[c * NP4 + idx];
            float ivA[4] = {iv.x, iv.y, iv.z, iv.w};
            float rvA[4] = {rv.x, rv.y, rv.z, rv.w};
            #pragma unroll
            for (int l = 0; l < 4; l++) {
                float im = dn255(ivA[l]) * msA[l];
                float rm = dn255(rvA[l]) * msA[l];
                float match = tA[l] ? stab[c * NB + (int)binof(rm)] : rm;
                acc += fabsf(im - match);
            }
        }
    }

    // block reduce -> double atomic
    float s = warpReduceSum(acc);
    __shared__ float ws[32];
    int lane = threadIdx.x & 31, w = threadIdx.x >> 5;
    if (lane == 0) ws[w] = s;
    __syncthreads();
    if (w == 0) {
        float v = (lane < (int)(blockDim.x >> 5)) ? ws[lane] : 0.0f;
        v = warpReduceSum(v);
        if (lane == 0) atomicAdd(&g_acc, (double)v);
    }
}

// ---------------- K5: finalize ----------------
__global__ void k_finalize(float* out) {
    out[0] = (float)(g_acc / (double)(3.0 * (double)HH));
}

// ---------------- launch ----------------
extern "C" void kernel_launch(void* const* d_in, const int* in_sizes, int n_in,
                              void* d_out, int out_size)
{
    const float* input_data  = (const float*)d_in[0];
    const float* target_data = (const float*)d_in[1];
    const float* ref         = (const float*)d_in[2];
    const float* mask_src    = (const float*)d_in[3];
    const float* mask_tar    = (const float*)d_in[4];
    const int* idx0 = (const int*)d_in[5];
    const int* idx1 = (const int*)d_in[6];
    const int* idx2 = (const int*)d_in[7];
    const int* idx3 = (const int*)d_in[8];
    float* out = (float*)d_out;

    k_binify<<<HH / 4 / 256, 256>>>(ref, target_data, mask_src, mask_tar);
    k_sample<<<(NIDX / 4 + 255) / 256, 256>>>(idx0, idx1, idx2, idx3);
    k_tables<<<1, 256>>>();
    k_loss<<<2048, 256>>>(input_data, ref, mask_src);
    k_finalize<<<1, 1>>>(out);
}

// round 5
// speedup vs baseline: 1.6418x; 1.1440x over previous
#include <cuda_runtime.h>
#include <cuda_bf16.h>
#include <stdint.h>

#define Hdim 2048
#define HH   (Hdim * Hdim)        // 4194304
#define NIDX 2000000
#define NB   256
#define TOUCH_BIT 0x01000000u

// ---------------- device scratch (no allocations allowed) ----------------
__device__ unsigned int  g_hist[6 * NB];      // [0..2]=dst(ref_masked), [3..5]=ref(target_masked)
__device__ unsigned int  g_bin_ref[HH];       // bits0-23: packed 3-ch bins of ref_masked; bit24: touched
__device__ unsigned int  g_bin_tgt[HH];       // packed 3-channel bins of target_masked
__device__ float         g_table[3 * NB];
__device__ double        g_acc;
__device__ unsigned int  g_done;              // ticket counter for fused finalize (zero-init)

// ---------------- helpers ----------------
__device__ __forceinline__ float dn255(float x) {
    float v = (x + 1.0f) * 0.5f;
    v = fminf(fmaxf(v, 0.0f), 1.0f);
    return v * 255.0f;
}
__device__ __forceinline__ unsigned int binof(float v) {
    int b = (int)v;                  // v >= 0, trunc == floor
    b = b < 0 ? 0 : b;
    return (unsigned int)(b > 255 ? 255 : b);
}
__device__ __forceinline__ float warpReduceSum(float v) {
    #pragma unroll
    for (int o = 16; o > 0; o >>= 1) v += __shfl_down_sync(0xffffffffu, v, o);
    return v;
}

// ---------------- K1: packed per-pixel bins (coalesced stream; also resets flags) ----------------
__global__ void __launch_bounds__(256) k_binify(
    const float* __restrict__ ref, const float* __restrict__ tgt,
    const float* __restrict__ msrc, const float* __restrict__ mtar)
{
    if (blockIdx.x == 0) {   // fold tiny init (hist consumed only after k_sample)
        for (int i = threadIdx.x; i < 6 * NB; i += blockDim.x) g_hist[i] = 0u;
        if (threadIdx.x == 0) g_acc = 0.0;
    }

    const int NP4 = HH / 4;
    int idx = blockIdx.x * blockDim.x + threadIdx.x;    // exactly NP4 threads launched
    if (idx >= NP4) return;

    const float4* m4  = reinterpret_cast<const float4*>(msrc);
    const float4* mt4 = reinterpret_cast<const float4*>(mtar);
    const float4* rf4 = reinterpret_cast<const float4*>(ref);
    const float4* tg4 = reinterpret_cast<const float4*>(tgt);

    float4 ms = m4[idx];
    float4 mt = mt4[idx];
    float msA[4] = {ms.x, ms.y, ms.z, ms.w};
    float mtA[4] = {mt.x, mt.y, mt.z, mt.w};

    unsigned int pr[4] = {0u, 0u, 0u, 0u};
    unsigned int pt[4] = {0u, 0u, 0u, 0u};
    #pragma unroll
    for (int c = 0; c < 3; c++) {
        float4 rv = rf4[c * NP4 + idx];
        float4 tv = tg4[c * NP4 + idx];
        float rvA[4] = {rv.x, rv.y, rv.z, rv.w};
        float tvA[4] = {tv.x, tv.y, tv.z, tv.w};
        #pragma unroll
        for (int l = 0; l < 4; l++) {
            pr[l] |= binof(dn255(rvA[l]) * msA[l]) << (8 * c);
            pt[l] |= binof(dn255(tvA[l]) * mtA[l]) << (8 * c);
        }
    }
    // full-word store also clears TOUCH_BIT from the previous replay
    reinterpret_cast<uint4*>(g_bin_ref)[idx] = make_uint4(pr[0], pr[1], pr[2], pr[3]);
    reinterpret_cast<uint4*>(g_bin_tgt)[idx] = make_uint4(pt[0], pt[1], pt[2], pt[3]);
}

// ---------------- K2: sample pass — L2-resident random loads + RED touched + shared hist ----------------
#define SPT 8   // samples per thread
__global__ void __launch_bounds__(256) k_sample(
    const int* __restrict__ i0, const int* __restrict__ i1,
    const int* __restrict__ i2, const int* __restrict__ i3)
{
    __shared__ unsigned int sh[6 * NB];
    for (int i = threadIdx.x; i < 6 * NB; i += blockDim.x) sh[i] = 0u;
    __syncthreads();

    unsigned int c0[6]   = {0, 0, 0, 0, 0, 0};
    unsigned int c255[6] = {0, 0, 0, 0, 0, 0};

    int t = blockIdx.x * blockDim.x + threadIdx.x;
    int k = t * SPT;
    if (k + SPT - 1 < NIDX) {
        int pA[SPT], qA[SPT];
        #pragma unroll
        for (int u = 0; u < SPT; u += 4) {
            int4 a0 = *reinterpret_cast<const int4*>(i0 + k + u);
            int4 a1 = *reinterpret_cast<const int4*>(i1 + k + u);
            int4 a2 = *reinterpret_cast<const int4*>(i2 + k + u);
            int4 a3 = *reinterpret_cast<const int4*>(i3 + k + u);
            pA[u + 0] = a0.x * Hdim + a1.x;  pA[u + 1] = a0.y * Hdim + a1.y;
            pA[u + 2] = a0.z * Hdim + a1.z;  pA[u + 3] = a0.w * Hdim + a1.w;
            qA[u + 0] = a2.x * Hdim + a3.x;  qA[u + 1] = a2.y * Hdim + a3.y;
            qA[u + 2] = a2.z * Hdim + a3.z;  qA[u + 3] = a2.w * Hdim + a3.w;
        }
        unsigned int wr[SPT], wt[SPT];
        #pragma unroll
        for (int l = 0; l < SPT; l++) {       // fire all independent accesses: MLP = 2*SPT
            wr[l] = __ldg(g_bin_ref + pA[l]);
            wt[l] = __ldg(g_bin_tgt + qA[l]);
            atomicOr(&g_bin_ref[pA[l]], TOUCH_BIT);   // no-return RED, same sector as load
        }
        #pragma unroll
        for (int l = 0; l < SPT; l++) {
            #pragma unroll
            for (int c = 0; c < 3; c++) {
                unsigned int b = (wr[l] >> (8 * c)) & 255u;
                if (b == 0u)        c0[c]++;
                else if (b == 255u) c255[c]++;
                else                atomicAdd(&sh[c * NB + b], 1u);
                unsigned int b2 = (wt[l] >> (8 * c)) & 255u;
                if (b2 == 0u)        c0[3 + c]++;
                else if (b2 == 255u) c255[3 + c]++;
                else                 atomicAdd(&sh[(3 + c) * NB + b2], 1u);
            }
        }
    } else {
        for (; k < NIDX; k++) {
            int p = i0[k] * Hdim + i1[k];
            int q = i2[k] * Hdim + i3[k];
            unsigned int wr = __ldg(g_bin_ref + p);
            unsigned int wt = __ldg(g_bin_tgt + q);
            atomicOr(&g_bin_ref[p], TOUCH_BIT);
            #pragma unroll
            for (int c = 0; c < 3; c++) {
                unsigned int b = (wr >> (8 * c)) & 255u;
                if (b == 0u)        c0[c]++;
                else if (b == 255u) c255[c]++;
                else                atomicAdd(&sh[c * NB + b], 1u);
                unsigned int b2 = (wt >> (8 * c)) & 255u;
                if (b2 == 0u)        c0[3 + c]++;
                else if (b2 == 255u) c255[3 + c]++;
                else                 atomicAdd(&sh[(3 + c) * NB + b2], 1u);
            }
        }
    }

    #pragma unroll
    for (int h = 0; h < 6; h++) {
        if (c0[h])   atomicAdd(&sh[h * NB + 0],   c0[h]);
        if (c255[h]) atomicAdd(&sh[h * NB + 255], c255[h]);
    }
    __syncthreads();
    for (int i = threadIdx.x; i < 6 * NB; i += blockDim.x) {
        unsigned int v = sh[i];
        if (v) atomicAdd(&g_hist[i], v);
    }
}

// ---------------- K3: CDFs (parallel integer scan) + transfer tables ----------------
__global__ void k_tables() {
    __shared__ unsigned int s0[NB], s1[NB];
    __shared__ float r[3][NB];   // cdf_dst
    __shared__ float a[3][NB];   // cdf_ref
    int i = threadIdx.x;

    for (int h = 0; h < 6; h++) {
        s0[i] = g_hist[h * NB + i];
        __syncthreads();
        unsigned int* src = s0; unsigned int* dst = s1;
        #pragma unroll
        for (int off = 1; off < NB; off <<= 1) {   // Hillis-Steele, exact integer adds
            unsigned int v = src[i];
            if (i >= off) v += src[i - off];
            dst[i] = v;
            __syncthreads();
            unsigned int* tmpp = src; src = dst; dst = tmpp;
        }
        float tot = (float)src[NB - 1];
        float v = (float)src[i] / tot;             // matches jnp: exact int in f32, then divide
        if (h < 3) r[h][i] = v; else a[h - 3][i] = v;
        __syncthreads();
    }

    #pragma unroll
    for (int c = 0; c < 3; c++) {
        float tbl;
        if (i == 0)           tbl = 0.0f;
        else if (i == NB - 1) tbl = 255.0f;
        else {
            float ri = r[c][i];
            int j = -1;
            for (int jj = 1; jj < NB; jj++) {
                if (ri >= a[c][jj - 1] && ri <= a[c][jj]) { j = jj; break; }
            }
            tbl = (j >= 0) ? (float)j : (float)i;
        }
        g_table[c * NB + i] = tbl;
    }
}

// ---------------- K4: loss over all pixels (pure-read stream) + fused finalize ----------------
__global__ void __launch_bounds__(256) k_loss(
    const float* __restrict__ inp, const float* __restrict__ ref,
    const float* __restrict__ msrc, float* __restrict__ out)
{
    __shared__ float stab[3 * NB];
    for (int i = threadIdx.x; i < 3 * NB; i += blockDim.x) stab[i] = g_table[i];
    __syncthreads();

    const float4* m4  = reinterpret_cast<const float4*>(msrc);
    const float4* in4 = reinterpret_cast<const float4*>(inp);
    const float4* rf4 = reinterpret_cast<const float4*>(ref);
    const uint4*  b4  = reinterpret_cast<const uint4*>(g_bin_ref);

    float acc = 0.0f;
    int stride = gridDim.x * blockDim.x;
    const int NP4 = HH / 4;
    for (int idx = blockIdx.x * blockDim.x + threadIdx.x; idx < NP4; idx += stride) {
        float4 ms = m4[idx];
        uint4  bw = b4[idx];
        float msA[4] = {ms.x, ms.y, ms.z, ms.w};
        unsigned int wA[4] = {bw.x, bw.y, bw.z, bw.w};
        #pragma unroll
        for (int c = 0; c < 3; c++) {
            float4 iv = in4[c * NP4 + idx];
            float4 rv = rf4[c * NP4 + idx];
            float ivA[4] = {iv.x, iv.y, iv.z, iv.w};
            float rvA[4] = {rv.x, rv.y, rv.z, rv.w};
            #pragma unroll
            for (int l = 0; l < 4; l++) {
                float im = dn255(ivA[l]) * msA[l];
                float rm = dn255(rvA[l]) * msA[l];
                float match = (wA[l] & TOUCH_BIT)
                            ? stab[c * NB + (int)((wA[l] >> (8 * c)) & 255u)]
                            : rm;
                acc += fabsf(im - match);
            }
        }
    }

    // block reduce -> double atomic; last block finalizes
    float s = warpReduceSum(acc);
    __shared__ float ws[32];
    int lane = threadIdx.x & 31, w = threadIdx.x >> 5;
    if (lane == 0) ws[w] = s;
    __syncthreads();
    if (w == 0) {
        float v = (lane < (int)(blockDim.x >> 5)) ? ws[lane] : 0.0f;
        v = warpReduceSum(v);
        if (lane == 0) {
            atomicAdd(&g_acc, (double)v);
            __threadfence();
            unsigned int ticket = atomicAdd(&g_done, 1u);
            if (ticket == gridDim.x - 1) {
                out[0] = (float)(g_acc / (double)(3.0 * (double)HH));
                g_done = 0u;   // reset for next replay
            }
        }
    }
}

// ---------------- launch ----------------
extern "C" void kernel_launch(void* const* d_in, const int* in_sizes, int n_in,
                              void* d_out, int out_size)
{
    const float* input_data  = (const float*)d_in[0];
    const float* target_data = (const float*)d_in[1];
    const float* ref         = (const float*)d_in[2];
    const float* mask_src    = (const float*)d_in[3];
    const float* mask_tar    = (const float*)d_in[4];
    const int* idx0 = (const int*)d_in[5];
    const int* idx1 = (const int*)d_in[6];
    const int* idx2 = (const int*)d_in[7];
    const int* idx3 = (const int*)d_in[8];
    float* out = (float*)d_out;

    k_binify<<<HH / 4 / 256, 256>>>(ref, target_data, mask_src, mask_tar);
    k_sample<<<(NIDX / SPT + 255) / 256, 256>>>(idx0, idx1, idx2, idx3);
    k_tables<<<1, 256>>>();
    k_loss<<<2048, 256>>>(input_data, ref, mask_src, out);
}